// round 1
// baseline (speedup 1.0000x reference)
#include <cuda_runtime.h>
#include <math.h>

// Problem constants (fixed shapes)
#define NN   50000
#define EE   800000
#define INF  256
#define HID  128
#define OUTF 64
#define NL   4

// ---------------- static device scratch (no allocations allowed) ----------------
__device__ float g_h0[NN * HID];     // residual state h0
__device__ float g_h [NN * HID];     // current activations h
__device__ float g_g [NN * HID];     // g = h @ Wr^T (pre-propagation)
__device__ float g_w [EE];           // CSR edge weights dinv[r]*dinv[c]
__device__ float g_dinv[NN];
__device__ int   g_counts[NN];
__device__ int   g_incl[NN];
__device__ int   g_indptr[NN + 1];
__device__ int   g_cursor[NN];
__device__ int   g_cols[EE];
__device__ int   g_chunksums[64];
__device__ int   g_chunkoff[64];
__device__ int   g_is64;

// ---------------- edge-index dtype detection (int32 vs int64 storage) ----------------
__global__ void detect_k(const int* __restrict__ ei32) {
    if (threadIdx.x == 0 && blockIdx.x == 0) {
        int any = 0;
        // int64 little-endian nonnegative values < 2^31 -> every odd word is 0.
        // int32 layout -> odd words are random node ids; 1024 samples all-zero is impossible.
        for (int i = 1; i < 2048; i += 2) any |= ei32[i];
        g_is64 = (any == 0) ? 1 : 0;
    }
}

__device__ __forceinline__ int edge_at(const int* __restrict__ ei32, int idx) {
    return g_is64 ? ei32[2 * idx] : ei32[idx];
}

// ---------------- graph build ----------------
__global__ void init_counts_k() {
    int i = blockIdx.x * blockDim.x + threadIdx.x;
    if (i < NN) g_counts[i] = 0;
}

__global__ void hist_k(const int* __restrict__ ei32) {
    int e = blockIdx.x * blockDim.x + threadIdx.x;
    if (e < EE) atomicAdd(&g_counts[edge_at(ei32, e)], 1);
}

__global__ void dinv_k() {
    int i = blockIdx.x * blockDim.x + threadIdx.x;
    if (i < NN) {
        float deg = (float)(g_counts[i] + 1);  // +1 self loop
        g_dinv[i] = rsqrtf(deg);
    }
}

// chunked exclusive scan of g_counts -> g_indptr
__global__ void scan1_k() {
    __shared__ int s[1024];
    int t = threadIdx.x;
    int base = blockIdx.x * 1024;
    int v = (base + t < NN) ? g_counts[base + t] : 0;
    s[t] = v;
    __syncthreads();
    for (int off = 1; off < 1024; off <<= 1) {
        int x = (t >= off) ? s[t - off] : 0;
        __syncthreads();
        s[t] += x;
        __syncthreads();
    }
    if (base + t < NN) g_incl[base + t] = s[t];
    if (t == 1023) g_chunksums[blockIdx.x] = s[1023];
}

__global__ void scan2_k() {
    if (threadIdx.x == 0) {
        int nch = (NN + 1023) / 1024;
        int run = 0;
        for (int i = 0; i < nch; i++) {
            g_chunkoff[i] = run;
            run += g_chunksums[i];
        }
    }
}

__global__ void scan3_k() {
    int i = blockIdx.x * blockDim.x + threadIdx.x;
    if (i < NN) {
        int v = g_chunkoff[i >> 10] + g_incl[i] - g_counts[i];  // exclusive
        g_indptr[i] = v;
        g_cursor[i] = v;
        if (i == 0) g_indptr[NN] = EE;
    }
}

__global__ void scatter_k(const int* __restrict__ ei32) {
    int e = blockIdx.x * blockDim.x + threadIdx.x;
    if (e < EE) {
        int r = edge_at(ei32, e);
        int c = edge_at(ei32, EE + e);
        int pos = atomicAdd(&g_cursor[r], 1);
        g_cols[pos] = c;
        g_w[pos] = g_dinv[r] * g_dinv[c];
    }
}

// ---------------- generic fp32 SIMT GEMM: C[M, BN] = A[M,K] @ B (+bias)(+relu) ----------------
// TRANSB: B given as [BN, K] row-major (compute A @ B^T), else B is [K, BN] row-major.
template<int BM, int BN, int BK, int TM, int TN, bool TRANSB, bool BIAS, bool RELU>
__global__ void gemm_k(const float* __restrict__ A, const float* __restrict__ B,
                       const float* __restrict__ bias, float* __restrict__ C,
                       int M, int K) {
    constexpr int NT = (BM / TM) * (BN / TN);
    __shared__ float As[BK][BM + 4];
    __shared__ float Bs[BK][BN + 4];

    int tid = threadIdx.x;
    int tx = tid % (BN / TN);
    int ty = tid / (BN / TN);
    int m0 = blockIdx.x * BM;

    float acc[TM][TN];
#pragma unroll
    for (int i = 0; i < TM; i++)
#pragma unroll
        for (int j = 0; j < TN; j++) acc[i][j] = 0.f;

    for (int k0 = 0; k0 < K; k0 += BK) {
        // load A tile (float4 along K), store transposed As[k][m]
        constexpr int A4 = BM * BK / 4;
#pragma unroll
        for (int i = 0; i < A4 / NT; i++) {
            int idx = tid + i * NT;
            int r = idx / (BK / 4);
            int kc = idx % (BK / 4);
            float4 v = make_float4(0.f, 0.f, 0.f, 0.f);
            if (m0 + r < M)
                v = *(const float4*)&A[(size_t)(m0 + r) * K + k0 + kc * 4];
            As[kc * 4 + 0][r] = v.x;
            As[kc * 4 + 1][r] = v.y;
            As[kc * 4 + 2][r] = v.z;
            As[kc * 4 + 3][r] = v.w;
        }
        // load B tile
        constexpr int B4 = BN * BK / 4;
#pragma unroll
        for (int i = 0; i < B4 / NT; i++) {
            int idx = tid + i * NT;
            if (TRANSB) {
                int n = idx / (BK / 4);
                int kc = idx % (BK / 4);
                float4 v = *(const float4*)&B[(size_t)n * K + k0 + kc * 4];
                Bs[kc * 4 + 0][n] = v.x;
                Bs[kc * 4 + 1][n] = v.y;
                Bs[kc * 4 + 2][n] = v.z;
                Bs[kc * 4 + 3][n] = v.w;
            } else {
                int k = idx / (BN / 4);
                int nc = idx % (BN / 4);
                float4 v = *(const float4*)&B[(size_t)(k0 + k) * BN + nc * 4];
                *(float4*)&Bs[k][nc * 4] = v;
            }
        }
        __syncthreads();

#pragma unroll
        for (int kk = 0; kk < BK; kk++) {
            float a_f[TM], b_f[TN];
#pragma unroll
            for (int i = 0; i < TM / 4; i++) {
                float4 v = *(const float4*)&As[kk][ty * TM + i * 4];
                a_f[i * 4 + 0] = v.x; a_f[i * 4 + 1] = v.y;
                a_f[i * 4 + 2] = v.z; a_f[i * 4 + 3] = v.w;
            }
#pragma unroll
            for (int j = 0; j < TN / 4; j++) {
                float4 v = *(const float4*)&Bs[kk][tx * TN + j * 4];
                b_f[j * 4 + 0] = v.x; b_f[j * 4 + 1] = v.y;
                b_f[j * 4 + 2] = v.z; b_f[j * 4 + 3] = v.w;
            }
#pragma unroll
            for (int i = 0; i < TM; i++)
#pragma unroll
                for (int j = 0; j < TN; j++)
                    acc[i][j] = fmaf(a_f[i], b_f[j], acc[i][j]);
        }
        __syncthreads();
    }

    // epilogue
#pragma unroll
    for (int i = 0; i < TM; i++) {
        int r = m0 + ty * TM + i;
        if (r < M) {
#pragma unroll
            for (int j = 0; j < TN; j += 4) {
                int c = tx * TN + j;
                float4 v;
                v.x = acc[i][j + 0];
                v.y = acc[i][j + 1];
                v.z = acc[i][j + 2];
                v.w = acc[i][j + 3];
                if (BIAS) {
                    v.x += bias[c + 0]; v.y += bias[c + 1];
                    v.z += bias[c + 2]; v.w += bias[c + 3];
                }
                if (RELU) {
                    v.x = fmaxf(v.x, 0.f); v.y = fmaxf(v.y, 0.f);
                    v.z = fmaxf(v.z, 0.f); v.w = fmaxf(v.w, 0.f);
                }
                *(float4*)&C[(size_t)r * BN + c] = v;
            }
        }
    }
}

// ---------------- fused SpMM + self-loop + epsilon residual + ReLU ----------------
// z = 6*g - 3*A_hat(g);  h0 = (1+tanh(eps_l))*h0 + z;  h = relu(h0)
// One block of 128 threads per node (one feature per thread; gathers coalesce to 512B).
__global__ void spmm_res_k(const float* __restrict__ eps, int layer) {
    int i = blockIdx.x;
    int f = threadIdx.x;
    int s = g_indptr[i];
    int e = g_indptr[i + 1];
    float acc = 0.f;
    int p = s;
    // unroll-by-2 to expose MLP on the gathers
    for (; p + 1 < e; p += 2) {
        int c0 = g_cols[p];     float w0 = g_w[p];
        int c1 = g_cols[p + 1]; float w1 = g_w[p + 1];
        float v0 = g_g[(size_t)c0 * HID + f];
        float v1 = g_g[(size_t)c1 * HID + f];
        acc = fmaf(w0, v0, acc);
        acc = fmaf(w1, v1, acc);
    }
    if (p < e) {
        int c0 = g_cols[p];
        acc = fmaf(g_w[p], g_g[(size_t)c0 * HID + f], acc);
    }
    float gi = g_g[(size_t)i * HID + f];
    float di = g_dinv[i];
    float z = (6.f - 3.f * di * di) * gi - 3.f * acc;
    float a = 1.f + tanhf(eps[layer]);
    float h0v = fmaf(a, g_h0[(size_t)i * HID + f], z);
    g_h0[(size_t)i * HID + f] = h0v;
    g_h[(size_t)i * HID + f] = fmaxf(h0v, 0.f);
}

// ---------------- launch ----------------
extern "C" void kernel_launch(void* const* d_in, const int* in_sizes, int n_in,
                              void* d_out, int out_size) {
    const float* x   = (const float*)d_in[0];
    const float* W1  = (const float*)d_in[1];
    const float* b1  = (const float*)d_in[2];
    const float* Wr  = (const float*)d_in[3];
    const float* eps = (const float*)d_in[4];
    const float* W2  = (const float*)d_in[5];
    const float* b2  = (const float*)d_in[6];
    const int*   ei  = (const int*)d_in[7];  // int32 or int64 storage, detected on device
    float* out = (float*)d_out;

    float *h0p, *hp, *gp;
    cudaGetSymbolAddress((void**)&h0p, g_h0);
    cudaGetSymbolAddress((void**)&hp,  g_h);
    cudaGetSymbolAddress((void**)&gp,  g_g);

    // --- graph build ---
    detect_k<<<1, 32>>>(ei);
    init_counts_k<<<(NN + 255) / 256, 256>>>();
    hist_k<<<(EE + 255) / 256, 256>>>(ei);
    dinv_k<<<(NN + 255) / 256, 256>>>();
    scan1_k<<<(NN + 1023) / 1024, 1024>>>();
    scan2_k<<<1, 32>>>();
    scan3_k<<<(NN + 255) / 256, 256>>>();
    scatter_k<<<(EE + 255) / 256, 256>>>(ei);

    int gblocks = (NN + 127) / 128;

    // --- lin1: h0 = relu(x @ W1 + b1) ---
    gemm_k<128, 128, 16, 8, 8, false, true, true>
        <<<gblocks, 256>>>(x, W1, b1, h0p, NN, INF);

    // --- 4 propagation layers ---
    for (int l = 0; l < NL; l++) {
        const float* src = (l == 0) ? h0p : hp;
        // g = h @ Wr[l]^T   (Wr[l] is [H,H] row-major -> TRANSB)
        gemm_k<128, 128, 16, 8, 8, true, false, false>
            <<<gblocks, 256>>>(src, Wr + (size_t)l * HID * HID, nullptr, gp, NN, HID);
        // z + residual + relu (fused)
        spmm_res_k<<<NN, HID>>>(eps, l);
    }

    // --- lin2: out = h @ W2 + b2 ---
    gemm_k<128, 64, 16, 8, 4, false, true, false>
        <<<gblocks, 256>>>(hp, W2, b2, out, NN, HID);
}

// round 2
// speedup vs baseline: 1.0024x; 1.0024x over previous
#include <cuda_runtime.h>
#include <math.h>
#include <stdint.h>

// Problem constants (fixed shapes)
#define NN   50000
#define EE   800000
#define INF  256
#define HID  128
#define OUTF 64
#define NL   4

// ---------------- static device scratch ----------------
__device__ float g_h0[NN * HID];
__device__ float g_h [NN * HID];
__device__ float g_g [NN * HID];
__device__ float g_w [EE];
__device__ float g_dinv[NN];
__device__ int   g_counts[NN];
__device__ int   g_incl[NN];
__device__ int   g_indptr[NN + 1];
__device__ int   g_cursor[NN];
__device__ int   g_cols[EE];
__device__ int   g_chunksums[64];
__device__ int   g_chunkoff[64];
__device__ int   g_is64;

// ---------------- edge-index dtype detection (int32 vs int64 storage) ----------------
__global__ void detect_k(const int* __restrict__ ei32) {
    if (threadIdx.x == 0 && blockIdx.x == 0) {
        int any = 0;
        for (int i = 1; i < 2048; i += 2) any |= ei32[i];
        g_is64 = (any == 0) ? 1 : 0;
    }
}

__device__ __forceinline__ int edge_at(const int* __restrict__ ei32, int idx) {
    return g_is64 ? ei32[2 * idx] : ei32[idx];
}

// ---------------- graph build ----------------
__global__ void hist_k(const int* __restrict__ ei32) {
    int e = blockIdx.x * blockDim.x + threadIdx.x;
    if (e < EE) atomicAdd(&g_counts[edge_at(ei32, e)], 1);
}

__global__ void dinv_k() {
    int i = blockIdx.x * blockDim.x + threadIdx.x;
    if (i < NN) {
        float deg = (float)(g_counts[i] + 1);  // +1 self loop
        g_dinv[i] = rsqrtf(deg);
    }
}

__global__ void scan1_k() {
    __shared__ int s[1024];
    int t = threadIdx.x;
    int base = blockIdx.x * 1024;
    int v = (base + t < NN) ? g_counts[base + t] : 0;
    s[t] = v;
    __syncthreads();
    for (int off = 1; off < 1024; off <<= 1) {
        int x = (t >= off) ? s[t - off] : 0;
        __syncthreads();
        s[t] += x;
        __syncthreads();
    }
    if (base + t < NN) g_incl[base + t] = s[t];
    if (t == 1023) g_chunksums[blockIdx.x] = s[1023];
}

__global__ void scan2_k() {
    if (threadIdx.x == 0) {
        int nch = (NN + 1023) / 1024;
        int run = 0;
        for (int i = 0; i < nch; i++) {
            g_chunkoff[i] = run;
            run += g_chunksums[i];
        }
    }
}

__global__ void scan3_k() {
    int i = blockIdx.x * blockDim.x + threadIdx.x;
    if (i < NN) {
        int v = g_chunkoff[i >> 10] + g_incl[i] - g_counts[i];
        g_indptr[i] = v;
        g_cursor[i] = v;
        if (i == 0) g_indptr[NN] = EE;
    }
}

__global__ void scatter_k(const int* __restrict__ ei32) {
    int e = blockIdx.x * blockDim.x + threadIdx.x;
    if (e < EE) {
        int r = edge_at(ei32, e);
        int c = edge_at(ei32, EE + e);
        int pos = atomicAdd(&g_cursor[r], 1);
        g_cols[pos] = c;
        g_w[pos] = g_dinv[r] * g_dinv[c];
    }
}

// ---------------- tf32 split helpers ----------------
__device__ __forceinline__ void split_tf32(float a, uint32_t& hi, uint32_t& lo) {
    asm("cvt.rna.tf32.f32 %0, %1;" : "=r"(hi) : "f"(a));
    float r = a - __uint_as_float(hi);
    asm("cvt.rna.tf32.f32 %0, %1;" : "=r"(lo) : "f"(r));
}

__device__ __forceinline__ void mma_tf32(float* d, const uint32_t* a, const uint32_t* b) {
    asm volatile(
        "mma.sync.aligned.m16n8k8.row.col.f32.tf32.tf32.f32 "
        "{%0,%1,%2,%3}, {%4,%5,%6,%7}, {%8,%9}, {%0,%1,%2,%3};\n"
        : "+f"(d[0]), "+f"(d[1]), "+f"(d[2]), "+f"(d[3])
        : "r"(a[0]), "r"(a[1]), "r"(a[2]), "r"(a[3]), "r"(b[0]), "r"(b[1]));
}

// ---------------- 3xTF32 tensor-core GEMM ----------------
// C[M, BN] = A[M,K] @ B (+bias)(+relu).  BM=128, BK=16, 256 threads (8 warps 4x2).
// TRANSB: B is [BN, K] row-major (A @ B^T), else [K, BN] row-major.
template<int BN, bool TRANSB, bool BIAS, bool RELU>
__global__ void __launch_bounds__(256) mma_gemm_k(
    const float* __restrict__ A, const float* __restrict__ B,
    const float* __restrict__ bias, float* __restrict__ C, int M, int K)
{
    constexpr int BM = 128, BK = 16;
    constexpr int ASTR = BK + 4;                     // 20: conflict-free A frag LDS
    constexpr int BSTR = (BN == 128) ? 136 : 72;     // stride ≡ 8 mod 32
    constexpr int WN = BN / 2;
    constexpr int NTN = WN / 8;                      // n-tiles per warp (8 or 4)

    __shared__ uint32_t As_hi[BM * ASTR];
    __shared__ uint32_t As_lo[BM * ASTR];
    __shared__ uint32_t Bs_hi[BK * BSTR];
    __shared__ uint32_t Bs_lo[BK * BSTR];

    const int tid = threadIdx.x;
    const int warp = tid >> 5, lane = tid & 31;
    const int wm = warp >> 1, wn = warp & 1;
    const int grp = lane >> 2, tig = lane & 3;
    const int m0 = blockIdx.x * BM;

    float acc[2][NTN][4];
#pragma unroll
    for (int i = 0; i < 2; i++)
#pragma unroll
        for (int j = 0; j < NTN; j++)
#pragma unroll
            for (int q = 0; q < 4; q++) acc[i][j][q] = 0.f;

    for (int k0 = 0; k0 < K; k0 += BK) {
        // --- load A tile: 128x16, float4 per thread, 2 iterations ---
#pragma unroll
        for (int it = 0; it < 2; it++) {
            int idx = tid + it * 256;
            int r = idx >> 2, kc = idx & 3;
            float4 v = make_float4(0.f, 0.f, 0.f, 0.f);
            if (m0 + r < M)
                v = *(const float4*)&A[(size_t)(m0 + r) * K + k0 + kc * 4];
            uint32_t h0, l0, h1, l1, h2, l2, h3, l3;
            split_tf32(v.x, h0, l0);
            split_tf32(v.y, h1, l1);
            split_tf32(v.z, h2, l2);
            split_tf32(v.w, h3, l3);
            uint32_t* ph = &As_hi[r * ASTR + kc * 4];
            uint32_t* pl = &As_lo[r * ASTR + kc * 4];
            ph[0] = h0; ph[1] = h1; ph[2] = h2; ph[3] = h3;
            pl[0] = l0; pl[1] = l1; pl[2] = l2; pl[3] = l3;
        }
        // --- load B tile ---
        constexpr int B4 = BN * BK / 4;  // 512 (BN=128) or 256 (BN=64)
#pragma unroll
        for (int it = 0; it < B4 / 256; it++) {
            int idx = tid + it * 256;
            if (TRANSB) {
                int n = idx >> 2, kc = idx & 3;
                float4 v = *(const float4*)&B[(size_t)n * K + k0 + kc * 4];
                uint32_t h, l;
                split_tf32(v.x, h, l); Bs_hi[(kc*4+0)*BSTR + n] = h; Bs_lo[(kc*4+0)*BSTR + n] = l;
                split_tf32(v.y, h, l); Bs_hi[(kc*4+1)*BSTR + n] = h; Bs_lo[(kc*4+1)*BSTR + n] = l;
                split_tf32(v.z, h, l); Bs_hi[(kc*4+2)*BSTR + n] = h; Bs_lo[(kc*4+2)*BSTR + n] = l;
                split_tf32(v.w, h, l); Bs_hi[(kc*4+3)*BSTR + n] = h; Bs_lo[(kc*4+3)*BSTR + n] = l;
            } else {
                int k = idx / (BN / 4), nc = idx % (BN / 4);
                float4 v = *(const float4*)&B[(size_t)(k0 + k) * BN + nc * 4];
                uint32_t h0, l0, h1, l1, h2, l2, h3, l3;
                split_tf32(v.x, h0, l0);
                split_tf32(v.y, h1, l1);
                split_tf32(v.z, h2, l2);
                split_tf32(v.w, h3, l3);
                uint32_t* ph = &Bs_hi[k * BSTR + nc * 4];
                uint32_t* pl = &Bs_lo[k * BSTR + nc * 4];
                ph[0] = h0; ph[1] = h1; ph[2] = h2; ph[3] = h3;
                pl[0] = l0; pl[1] = l1; pl[2] = l2; pl[3] = l3;
            }
        }
        __syncthreads();

#pragma unroll
        for (int kt = 0; kt < 2; kt++) {
            uint32_t ah[2][4], al[2][4];
#pragma unroll
            for (int i = 0; i < 2; i++) {
                int row = wm * 32 + i * 16 + grp;
                int ck = kt * 8 + tig;
                ah[i][0] = As_hi[row * ASTR + ck];
                ah[i][1] = As_hi[(row + 8) * ASTR + ck];
                ah[i][2] = As_hi[row * ASTR + ck + 4];
                ah[i][3] = As_hi[(row + 8) * ASTR + ck + 4];
                al[i][0] = As_lo[row * ASTR + ck];
                al[i][1] = As_lo[(row + 8) * ASTR + ck];
                al[i][2] = As_lo[row * ASTR + ck + 4];
                al[i][3] = As_lo[(row + 8) * ASTR + ck + 4];
            }
#pragma unroll
            for (int j = 0; j < NTN; j++) {
                int n = wn * WN + j * 8 + grp;
                int kk = kt * 8 + tig;
                uint32_t bh[2], bl[2];
                bh[0] = Bs_hi[kk * BSTR + n];
                bh[1] = Bs_hi[(kk + 4) * BSTR + n];
                bl[0] = Bs_lo[kk * BSTR + n];
                bl[1] = Bs_lo[(kk + 4) * BSTR + n];
#pragma unroll
                for (int i = 0; i < 2; i++) {
                    mma_tf32(acc[i][j], ah[i], bh);   // hi * hi
                    mma_tf32(acc[i][j], al[i], bh);   // lo * hi
                    mma_tf32(acc[i][j], ah[i], bl);   // hi * lo
                }
            }
        }
        __syncthreads();
    }

    // --- epilogue ---
#pragma unroll
    for (int i = 0; i < 2; i++) {
#pragma unroll
        for (int j = 0; j < NTN; j++) {
            int col = wn * WN + j * 8 + tig * 2;
            int row0 = m0 + wm * 32 + i * 16 + grp;
            int row1 = row0 + 8;
            float2 v0 = make_float2(acc[i][j][0], acc[i][j][1]);
            float2 v1 = make_float2(acc[i][j][2], acc[i][j][3]);
            if (BIAS) {
                float bx = bias[col], by = bias[col + 1];
                v0.x += bx; v0.y += by;
                v1.x += bx; v1.y += by;
            }
            if (RELU) {
                v0.x = fmaxf(v0.x, 0.f); v0.y = fmaxf(v0.y, 0.f);
                v1.x = fmaxf(v1.x, 0.f); v1.y = fmaxf(v1.y, 0.f);
            }
            if (row0 < M) *(float2*)&C[(size_t)row0 * BN + col] = v0;
            if (row1 < M) *(float2*)&C[(size_t)row1 * BN + col] = v1;
        }
    }
}

// ---------------- fused SpMM + self-loop + epsilon residual + ReLU ----------------
__global__ void spmm_res_k(const float* __restrict__ eps, int layer) {
    int i = blockIdx.x;
    int f = threadIdx.x;
    int s = g_indptr[i];
    int e = g_indptr[i + 1];
    float acc0 = 0.f, acc1 = 0.f, acc2 = 0.f, acc3 = 0.f;
    int p = s;
    for (; p + 3 < e; p += 4) {
        int c0 = g_cols[p];     float w0 = g_w[p];
        int c1 = g_cols[p + 1]; float w1 = g_w[p + 1];
        int c2 = g_cols[p + 2]; float w2 = g_w[p + 2];
        int c3 = g_cols[p + 3]; float w3 = g_w[p + 3];
        float v0 = g_g[(size_t)c0 * HID + f];
        float v1 = g_g[(size_t)c1 * HID + f];
        float v2 = g_g[(size_t)c2 * HID + f];
        float v3 = g_g[(size_t)c3 * HID + f];
        acc0 = fmaf(w0, v0, acc0);
        acc1 = fmaf(w1, v1, acc1);
        acc2 = fmaf(w2, v2, acc2);
        acc3 = fmaf(w3, v3, acc3);
    }
    for (; p < e; p++) {
        int c0 = g_cols[p];
        acc0 = fmaf(g_w[p], g_g[(size_t)c0 * HID + f], acc0);
    }
    float acc = (acc0 + acc1) + (acc2 + acc3);
    float gi = g_g[(size_t)i * HID + f];
    float di = g_dinv[i];
    float z = (6.f - 3.f * di * di) * gi - 3.f * acc;
    float a = 1.f + tanhf(eps[layer]);
    float h0v = fmaf(a, g_h0[(size_t)i * HID + f], z);
    g_h0[(size_t)i * HID + f] = h0v;
    g_h[(size_t)i * HID + f] = fmaxf(h0v, 0.f);
}

// ---------------- launch ----------------
extern "C" void kernel_launch(void* const* d_in, const int* in_sizes, int n_in,
                              void* d_out, int out_size) {
    const float* x   = (const float*)d_in[0];
    const float* W1  = (const float*)d_in[1];
    const float* b1  = (const float*)d_in[2];
    const float* Wr  = (const float*)d_in[3];
    const float* eps = (const float*)d_in[4];
    const float* W2  = (const float*)d_in[5];
    const float* b2  = (const float*)d_in[6];
    const int*   ei  = (const int*)d_in[7];
    float* out = (float*)d_out;

    float *h0p, *hp, *gp;
    int* cntp;
    cudaGetSymbolAddress((void**)&h0p, g_h0);
    cudaGetSymbolAddress((void**)&hp,  g_h);
    cudaGetSymbolAddress((void**)&gp,  g_g);
    cudaGetSymbolAddress((void**)&cntp, g_counts);

    // --- graph build ---
    detect_k<<<1, 32>>>(ei);
    cudaMemsetAsync(cntp, 0, NN * sizeof(int));
    hist_k<<<(EE + 255) / 256, 256>>>(ei);
    dinv_k<<<(NN + 255) / 256, 256>>>();
    scan1_k<<<(NN + 1023) / 1024, 1024>>>();
    scan2_k<<<1, 32>>>();
    scan3_k<<<(NN + 255) / 256, 256>>>();
    scatter_k<<<(EE + 255) / 256, 256>>>(ei);

    int gblocks = (NN + 127) / 128;

    // --- lin1: h0 = relu(x @ W1 + b1) ---
    mma_gemm_k<128, false, true, true><<<gblocks, 256>>>(x, W1, b1, h0p, NN, INF);

    // --- 4 propagation layers ---
    for (int l = 0; l < NL; l++) {
        const float* src = (l == 0) ? h0p : hp;
        mma_gemm_k<128, true, false, false>
            <<<gblocks, 256>>>(src, Wr + (size_t)l * HID * HID, nullptr, gp, NN, HID);
        spmm_res_k<<<NN, HID>>>(eps, l);
    }

    // --- lin2: out = h @ W2 + b2 ---
    mma_gemm_k<64, false, true, false><<<gblocks, 256>>>(hp, W2, b2, out, NN, HID);
}

// round 4
// speedup vs baseline: 1.4147x; 1.4113x over previous
#include <cuda_runtime.h>
#include <cuda_fp16.h>
#include <math.h>
#include <stdint.h>

// Problem constants (fixed shapes)
#define NN   50000
#define EE   800000
#define INF  256
#define HID  128
#define OUTF 64
#define NL   4

// ---------------- static device scratch ----------------
__device__ float  g_h0[NN * HID];
__device__ float  g_h [NN * HID];
__device__ float  g_g [NN * HID];
__device__ __half g_gh[NN * HID];    // fp16 copy of g for SpMM gather
__device__ float  g_w [EE];
__device__ float  g_dinv[NN];
__device__ int    g_counts[NN];
__device__ int    g_incl[NN];
__device__ int    g_indptr[NN + 1];
__device__ int    g_cursor[NN];
__device__ int    g_cols[EE];
__device__ int    g_chunksums[64];
__device__ int    g_is64;

// ---------------- edge dtype detect + zero counts (fused, launch #1) ----------------
__global__ void detect_zero_k(const int* __restrict__ ei32) {
    int i = blockIdx.x * blockDim.x + threadIdx.x;
    if (i < NN) g_counts[i] = 0;
    if (blockIdx.x == 0) {
        __shared__ int s_any;
        if (threadIdx.x == 0) s_any = 0;
        __syncthreads();
        int any = 0;
        for (int j = 1 + 2 * threadIdx.x; j < 8192; j += 2 * 256) any |= ei32[j];
        if (any) atomicOr(&s_any, 1);
        __syncthreads();
        if (threadIdx.x == 0) g_is64 = (s_any == 0) ? 1 : 0;
    }
}

__device__ __forceinline__ int edge_at(const int* __restrict__ ei32, int idx) {
    return g_is64 ? ei32[2 * idx] : ei32[idx];
}

// ---------------- graph build ----------------
__global__ void hist_k(const int* __restrict__ ei32) {   // launch #2
    int e = blockIdx.x * blockDim.x + threadIdx.x;
    if (e < EE) atomicAdd(&g_counts[edge_at(ei32, e)], 1);
}

__global__ void scan1_dinv_k() {                          // launch #3
    __shared__ int s[1024];
    int t = threadIdx.x;
    int base = blockIdx.x * 1024;
    int v = (base + t < NN) ? g_counts[base + t] : 0;
    if (base + t < NN) g_dinv[base + t] = rsqrtf((float)(v + 1));
    s[t] = v;
    __syncthreads();
    for (int off = 1; off < 1024; off <<= 1) {
        int x = (t >= off) ? s[t - off] : 0;
        __syncthreads();
        s[t] += x;
        __syncthreads();
    }
    if (base + t < NN) g_incl[base + t] = s[t];
    if (t == 1023) g_chunksums[blockIdx.x] = s[1023];
}

__global__ void scan23_k() {                              // launch #4
    __shared__ int s_off;
    int b = blockIdx.x;
    if (threadIdx.x < 32) {
        int v = 0;
        for (int k = threadIdx.x; k < b; k += 32) v += g_chunksums[k];
#pragma unroll
        for (int o = 16; o; o >>= 1) v += __shfl_down_sync(0xffffffffu, v, o);
        if (threadIdx.x == 0) s_off = v;
    }
    __syncthreads();
    int i = b * 1024 + threadIdx.x;
    if (i < NN) {
        int v = s_off + g_incl[i] - g_counts[i];   // exclusive prefix
        g_indptr[i] = v;
        g_cursor[i] = v;
        if (i == 0) g_indptr[NN] = EE;
    }
}

__global__ void scatter_k(const int* __restrict__ ei32) { // launch #5
    int e = blockIdx.x * blockDim.x + threadIdx.x;
    if (e < EE) {
        int r = edge_at(ei32, e);
        int c = edge_at(ei32, EE + e);
        int pos = atomicAdd(&g_cursor[r], 1);
        g_cols[pos] = c;
        g_w[pos] = g_dinv[r] * g_dinv[c];
    }
}

// ---------------- fp16 split helpers ----------------
__device__ __forceinline__ void split_h2(float x, float y, uint32_t& hi, uint32_t& lo) {
    __half2 h = __floats2half2_rn(x, y);
    float rx = x - __low2float(h);
    float ry = y - __high2float(h);
    __half2 l = __floats2half2_rn(rx, ry);
    hi = *(uint32_t*)&h;
    lo = *(uint32_t*)&l;
}

__device__ __forceinline__ void mma_f16(float* d, const uint32_t* a, const uint32_t* b) {
    asm volatile(
        "mma.sync.aligned.m16n8k16.row.col.f32.f16.f16.f32 "
        "{%0,%1,%2,%3}, {%4,%5,%6,%7}, {%8,%9}, {%0,%1,%2,%3};\n"
        : "+f"(d[0]), "+f"(d[1]), "+f"(d[2]), "+f"(d[3])
        : "r"(a[0]), "r"(a[1]), "r"(a[2]), "r"(a[3]), "r"(b[0]), "r"(b[1]));
}

// ---------------- 3xFP16-split tensor GEMM ----------------
// C[M, BN] = A[M,K] @ B (+bias)(+relu)(+half copy). BM=128, BK=32, 256 threads (8 warps 4x2).
// TRANSB: B is [BN, K] row-major (A @ B^T), else [K, BN] row-major.
// Shared tiles stored as half2 words, K-pair-major, stride 20 words (conflict-free frag LDS).
template<int BN, bool TRANSB, bool BIAS, bool RELU, bool WRITEH>
__global__ void __launch_bounds__(256) mma_gemm_k(
    const float* __restrict__ A, const float* __restrict__ B,
    const float* __restrict__ bias, float* __restrict__ C,
    __half* __restrict__ Ch, int M, int K)
{
    constexpr int BM = 128, BK = 32;
    constexpr int STR = 20;              // 16 half2 (32 halves) + 4 pad words
    constexpr int WN = BN / 2;
    constexpr int NTN = WN / 8;          // n-tiles per warp (8 or 4)

    __shared__ uint32_t As_hi[BM * STR];
    __shared__ uint32_t As_lo[BM * STR];
    __shared__ uint32_t Bs_hi[BN * STR];
    __shared__ uint32_t Bs_lo[BN * STR];

    const int tid = threadIdx.x;
    const int warp = tid >> 5, lane = tid & 31;
    const int wm = warp >> 1, wn = warp & 1;
    const int grp = lane >> 2, tig = lane & 3;
    const int m0 = blockIdx.x * BM;

    float acc[2][NTN][4];
#pragma unroll
    for (int i = 0; i < 2; i++)
#pragma unroll
        for (int j = 0; j < NTN; j++)
#pragma unroll
            for (int q = 0; q < 4; q++) acc[i][j][q] = 0.f;

    for (int k0 = 0; k0 < K; k0 += BK) {
        // --- A tile: 128x32 floats = 1024 float4, 4 iters ---
#pragma unroll
        for (int it = 0; it < 4; it++) {
            int idx = tid + it * 256;
            int r = idx >> 3, c = idx & 7;            // c: float4 within row
            float4 v = make_float4(0.f, 0.f, 0.f, 0.f);
            if (m0 + r < M) v = *(const float4*)&A[(size_t)(m0 + r) * K + k0 + c * 4];
            uint32_t h01, l01, h23, l23;
            split_h2(v.x, v.y, h01, l01);
            split_h2(v.z, v.w, h23, l23);
            As_hi[r * STR + c * 2]     = h01;
            As_hi[r * STR + c * 2 + 1] = h23;
            As_lo[r * STR + c * 2]     = l01;
            As_lo[r * STR + c * 2 + 1] = l23;
        }
        // --- B tile ---
        if (TRANSB) {
#pragma unroll
            for (int it = 0; it < (BN * 8) / 256; it++) {
                int idx = tid + it * 256;
                int n = idx >> 3, c = idx & 7;
                float4 v = *(const float4*)&B[(size_t)n * K + k0 + c * 4];
                uint32_t h01, l01, h23, l23;
                split_h2(v.x, v.y, h01, l01);
                split_h2(v.z, v.w, h23, l23);
                Bs_hi[n * STR + c * 2]     = h01;
                Bs_hi[n * STR + c * 2 + 1] = h23;
                Bs_lo[n * STR + c * 2]     = l01;
                Bs_lo[n * STR + c * 2 + 1] = l23;
            }
        } else {
            // B[K, BN]: coalesced read, scattered 16-bit smem stores
#pragma unroll
            for (int it = 0; it < (BK * BN / 4) / 256; it++) {
                int idx = tid + it * 256;
                int k = idx / (BN / 4), nc4 = (idx % (BN / 4)) * 4;
                float4 v = *(const float4*)&B[(size_t)(k0 + k) * BN + nc4];
                float vv[4] = {v.x, v.y, v.z, v.w};
#pragma unroll
                for (int q = 0; q < 4; q++) {
                    int n = nc4 + q;
                    __half h = __float2half_rn(vv[q]);
                    __half l = __float2half_rn(vv[q] - __half2float(h));
                    uint32_t off = (uint32_t)(n * STR + (k >> 1)) * 4u + (uint32_t)(k & 1) * 2u;
                    *(uint16_t*)((char*)Bs_hi + off) = *(uint16_t*)&h;
                    *(uint16_t*)((char*)Bs_lo + off) = *(uint16_t*)&l;
                }
            }
        }
        __syncthreads();

#pragma unroll
        for (int kt = 0; kt < 2; kt++) {
            const int kb = kt * 8;                    // half2 base index within row
            uint32_t ah[2][4], al[2][4];
#pragma unroll
            for (int i = 0; i < 2; i++) {
                int row = wm * 32 + i * 16 + grp;
                ah[i][0] = As_hi[row * STR + kb + tig];
                ah[i][1] = As_hi[(row + 8) * STR + kb + tig];
                ah[i][2] = As_hi[row * STR + kb + tig + 4];
                ah[i][3] = As_hi[(row + 8) * STR + kb + tig + 4];
                al[i][0] = As_lo[row * STR + kb + tig];
                al[i][1] = As_lo[(row + 8) * STR + kb + tig];
                al[i][2] = As_lo[row * STR + kb + tig + 4];
                al[i][3] = As_lo[(row + 8) * STR + kb + tig + 4];
            }
#pragma unroll
            for (int j = 0; j < NTN; j++) {
                int n = wn * WN + j * 8 + grp;
                uint32_t bh[2], bl[2];
                bh[0] = Bs_hi[n * STR + kb + tig];
                bh[1] = Bs_hi[n * STR + kb + tig + 4];
                bl[0] = Bs_lo[n * STR + kb + tig];
                bl[1] = Bs_lo[n * STR + kb + tig + 4];
#pragma unroll
                for (int i = 0; i < 2; i++) {
                    mma_f16(acc[i][j], ah[i], bh);   // hi * hi
                    mma_f16(acc[i][j], al[i], bh);   // lo * hi
                    mma_f16(acc[i][j], ah[i], bl);   // hi * lo
                }
            }
        }
        __syncthreads();
    }

    // --- epilogue ---
#pragma unroll
    for (int i = 0; i < 2; i++) {
#pragma unroll
        for (int j = 0; j < NTN; j++) {
            int col = wn * WN + j * 8 + tig * 2;
            int row0 = m0 + wm * 32 + i * 16 + grp;
            int row1 = row0 + 8;
            float2 v0 = make_float2(acc[i][j][0], acc[i][j][1]);
            float2 v1 = make_float2(acc[i][j][2], acc[i][j][3]);
            if (BIAS) {
                float bx = bias[col], by = bias[col + 1];
                v0.x += bx; v0.y += by;
                v1.x += bx; v1.y += by;
            }
            if (RELU) {
                v0.x = fmaxf(v0.x, 0.f); v0.y = fmaxf(v0.y, 0.f);
                v1.x = fmaxf(v1.x, 0.f); v1.y = fmaxf(v1.y, 0.f);
            }
            if (row0 < M) {
                *(float2*)&C[(size_t)row0 * BN + col] = v0;
                if (WRITEH) {
                    __half2 hv = __floats2half2_rn(v0.x, v0.y);
                    *(__half2*)&Ch[(size_t)row0 * BN + col] = hv;
                }
            }
            if (row1 < M) {
                *(float2*)&C[(size_t)row1 * BN + col] = v1;
                if (WRITEH) {
                    __half2 hv = __floats2half2_rn(v1.x, v1.y);
                    *(__half2*)&Ch[(size_t)row1 * BN + col] = hv;
                }
            }
        }
    }
}

// ---------------- fused SpMM (fp16 gather) + self-loop + residual + ReLU ----------------
// 256 threads = 4 nodes x 64 lanes; each lane owns a half2/float2 feature pair.
__global__ void __launch_bounds__(256) spmm_res_k(const float* __restrict__ eps, int layer) {
    int node = blockIdx.x * 4 + (threadIdx.x >> 6);
    int f2 = threadIdx.x & 63;
    if (node >= NN) return;
    int s = g_indptr[node];
    int e = g_indptr[node + 1];
    const uint32_t* gh = (const uint32_t*)g_gh;

    float a0x = 0.f, a0y = 0.f, a1x = 0.f, a1y = 0.f;
    float a2x = 0.f, a2y = 0.f, a3x = 0.f, a3y = 0.f;
    int p = s;
    for (; p + 3 < e; p += 4) {
        int   c0 = g_cols[p];     float w0 = g_w[p];
        int   c1 = g_cols[p + 1]; float w1 = g_w[p + 1];
        int   c2 = g_cols[p + 2]; float w2 = g_w[p + 2];
        int   c3 = g_cols[p + 3]; float w3 = g_w[p + 3];
        float2 v0 = __half22float2(*(const __half2*)&gh[c0 * 64 + f2]);
        float2 v1 = __half22float2(*(const __half2*)&gh[c1 * 64 + f2]);
        float2 v2 = __half22float2(*(const __half2*)&gh[c2 * 64 + f2]);
        float2 v3 = __half22float2(*(const __half2*)&gh[c3 * 64 + f2]);
        a0x = fmaf(w0, v0.x, a0x); a0y = fmaf(w0, v0.y, a0y);
        a1x = fmaf(w1, v1.x, a1x); a1y = fmaf(w1, v1.y, a1y);
        a2x = fmaf(w2, v2.x, a2x); a2y = fmaf(w2, v2.y, a2y);
        a3x = fmaf(w3, v3.x, a3x); a3y = fmaf(w3, v3.y, a3y);
    }
    for (; p < e; p++) {
        int c0 = g_cols[p]; float w0 = g_w[p];
        float2 v0 = __half22float2(*(const __half2*)&gh[c0 * 64 + f2]);
        a0x = fmaf(w0, v0.x, a0x); a0y = fmaf(w0, v0.y, a0y);
    }
    float accx = (a0x + a1x) + (a2x + a3x);
    float accy = (a0y + a1y) + (a2y + a3y);

    size_t base = (size_t)node * HID + f2 * 2;
    float2 gi = *(const float2*)&g_g[base];
    float di = g_dinv[node];
    float c6 = 6.f - 3.f * di * di;
    float zx = fmaf(c6, gi.x, -3.f * accx);
    float zy = fmaf(c6, gi.y, -3.f * accy);
    float a = 1.f + tanhf(eps[layer]);
    float2 h0v = *(const float2*)&g_h0[base];
    h0v.x = fmaf(a, h0v.x, zx);
    h0v.y = fmaf(a, h0v.y, zy);
    *(float2*)&g_h0[base] = h0v;
    float2 hv = make_float2(fmaxf(h0v.x, 0.f), fmaxf(h0v.y, 0.f));
    *(float2*)&g_h[base] = hv;
}

// ---------------- launch ----------------
extern "C" void kernel_launch(void* const* d_in, const int* in_sizes, int n_in,
                              void* d_out, int out_size) {
    const float* x   = (const float*)d_in[0];
    const float* W1  = (const float*)d_in[1];
    const float* b1  = (const float*)d_in[2];
    const float* Wr  = (const float*)d_in[3];
    const float* eps = (const float*)d_in[4];
    const float* W2  = (const float*)d_in[5];
    const float* b2  = (const float*)d_in[6];
    const int*   ei  = (const int*)d_in[7];
    float* out = (float*)d_out;

    float *h0p, *hp, *gp;
    __half* ghp;
    cudaGetSymbolAddress((void**)&h0p, g_h0);
    cudaGetSymbolAddress((void**)&hp,  g_h);
    cudaGetSymbolAddress((void**)&gp,  g_g);
    cudaGetSymbolAddress((void**)&ghp, g_gh);

    // --- graph build (5 kernels; ncu -s 5 -c 1 lands on lin1 GEMM below) ---
    detect_zero_k<<<(NN + 255) / 256, 256>>>(ei);
    hist_k<<<(EE + 255) / 256, 256>>>(ei);
    scan1_dinv_k<<<(NN + 1023) / 1024, 1024>>>();
    scan23_k<<<(NN + 1023) / 1024, 1024>>>();
    scatter_k<<<(EE + 255) / 256, 256>>>(ei);

    int gblocks = (NN + 127) / 128;  // 391

    // --- lin1: h0 = relu(x @ W1 + b1) ---
    mma_gemm_k<128, false, true, true, false>
        <<<gblocks, 256>>>(x, W1, b1, h0p, nullptr, NN, INF);

    // --- 4 propagation layers ---
    for (int l = 0; l < NL; l++) {
        const float* src = (l == 0) ? h0p : hp;
        mma_gemm_k<128, true, false, false, true>
            <<<gblocks, 256>>>(src, Wr + (size_t)l * HID * HID, nullptr, gp, ghp, NN, HID);
        spmm_res_k<<<(NN + 3) / 4, 256>>>(eps, l);
    }

    // --- lin2: out = h @ W2 + b2 ---
    mma_gemm_k<64, false, true, false, false>
        <<<gblocks, 256>>>(hp, W2, b2, out, nullptr, NN, HID);
}

// round 6
// speedup vs baseline: 1.5422x; 1.0901x over previous
#include <cuda_runtime.h>
#include <cuda_fp16.h>
#include <math.h>
#include <stdint.h>

// Problem constants (fixed shapes)
#define NN   50000
#define EE   800000
#define INF  256
#define HID  128
#define OUTF 64
#define NL   4

// ---------------- static device scratch ----------------
__device__ float  g_h0[NN * HID];       // residual state (fp32)
__device__ __half g_hs_hi[NN * HID];    // split activations: hi
__device__ __half g_hs_lo[NN * HID];    // split activations: lo
__device__ float  g_g [NN * HID];       // GEMM output g (fp32, self-loop term)
__device__ __half g_gh[NN * HID];       // fp16 copy of g for SpMM gather
__device__ float  g_w [EE];
__device__ float  g_dinv[NN];
__device__ int    g_counts[NN];
__device__ int    g_incl[NN];
__device__ int    g_indptr[NN + 1];
__device__ int    g_cursor[NN];
__device__ int    g_cols[EE];
__device__ int    g_chunksums[64];
__device__ int    g_is64;

// pre-split weights (K-major: B[n][k])
__device__ __half g_w1t_hi[HID * INF];       // [128][256] = W1^T
__device__ __half g_w1t_lo[HID * INF];
__device__ __half g_wrt_hi[NL * HID * HID];  // [4][128][128] = Wr (already n,k)
__device__ __half g_wrt_lo[NL * HID * HID];
__device__ __half g_w2t_hi[OUTF * HID];      // [64][128] = W2^T
__device__ __half g_w2t_lo[OUTF * HID];

// ---------------- weight split prep (launch #1) ----------------
__global__ void split_w_k(const float* __restrict__ W1, const float* __restrict__ Wr,
                          const float* __restrict__ W2) {
    int idx = blockIdx.x * blockDim.x + threadIdx.x;
    float v;
    __half* hi;
    __half* lo;
    int oidx;
    if (idx < HID * INF) {                       // W1^T: out[n*256+k] = W1[k*128+n]
        int n = idx >> 8, k = idx & 255;
        v = W1[k * HID + n];
        hi = g_w1t_hi; lo = g_w1t_lo; oidx = idx;
    } else if (idx < HID * INF + NL * HID * HID) {  // Wr direct copy-split
        int j = idx - HID * INF;
        v = Wr[j];
        hi = g_wrt_hi; lo = g_wrt_lo; oidx = j;
    } else if (idx < HID * INF + NL * HID * HID + OUTF * HID) {  // W2^T
        int j = idx - HID * INF - NL * HID * HID;
        int n = j >> 7, k = j & 127;
        v = W2[k * OUTF + n];
        hi = g_w2t_hi; lo = g_w2t_lo; oidx = j;
    } else return;
    __half h = __float2half_rn(v);
    hi[oidx] = h;
    lo[oidx] = __float2half_rn(v - __half2float(h));
}

// ---------------- edge dtype detect + zero counts (launch #2) ----------------
__global__ void detect_zero_k(const int* __restrict__ ei32) {
    int i = blockIdx.x * blockDim.x + threadIdx.x;
    if (i < NN) g_counts[i] = 0;
    if (blockIdx.x == 0) {
        __shared__ int s_any;
        if (threadIdx.x == 0) s_any = 0;
        __syncthreads();
        int any = 0;
        for (int j = 1 + 2 * threadIdx.x; j < 8192; j += 2 * 256) any |= ei32[j];
        if (any) atomicOr(&s_any, 1);
        __syncthreads();
        if (threadIdx.x == 0) g_is64 = (s_any == 0) ? 1 : 0;
    }
}

__device__ __forceinline__ int edge_at(const int* __restrict__ ei32, int idx) {
    return g_is64 ? ei32[2 * idx] : ei32[idx];
}

// ---------------- graph build ----------------
__global__ void hist_k(const int* __restrict__ ei32) {   // launch #3
    int e = blockIdx.x * blockDim.x + threadIdx.x;
    if (e < EE) atomicAdd(&g_counts[edge_at(ei32, e)], 1);
}

__global__ void scan1_dinv_k() {
    __shared__ int s[1024];
    int t = threadIdx.x;
    int base = blockIdx.x * 1024;
    int v = (base + t < NN) ? g_counts[base + t] : 0;
    if (base + t < NN) g_dinv[base + t] = rsqrtf((float)(v + 1));
    s[t] = v;
    __syncthreads();
    for (int off = 1; off < 1024; off <<= 1) {
        int x = (t >= off) ? s[t - off] : 0;
        __syncthreads();
        s[t] += x;
        __syncthreads();
    }
    if (base + t < NN) g_incl[base + t] = s[t];
    if (t == 1023) g_chunksums[blockIdx.x] = s[1023];
}

__global__ void scan23_k() {
    __shared__ int s_off;
    int b = blockIdx.x;
    if (threadIdx.x < 32) {
        int v = 0;
        for (int k = threadIdx.x; k < b; k += 32) v += g_chunksums[k];
#pragma unroll
        for (int o = 16; o; o >>= 1) v += __shfl_down_sync(0xffffffffu, v, o);
        if (threadIdx.x == 0) s_off = v;
    }
    __syncthreads();
    int i = b * 1024 + threadIdx.x;
    if (i < NN) {
        int v = s_off + g_incl[i] - g_counts[i];
        g_indptr[i] = v;
        g_cursor[i] = v;
        if (i == 0) g_indptr[NN] = EE;
    }
}

__global__ void scatter_k(const int* __restrict__ ei32) {
    int e = blockIdx.x * blockDim.x + threadIdx.x;
    if (e < EE) {
        int r = edge_at(ei32, e);
        int c = edge_at(ei32, EE + e);
        int pos = atomicAdd(&g_cursor[r], 1);
        g_cols[pos] = c;
        g_w[pos] = g_dinv[r] * g_dinv[c];
    }
}

// ---------------- fp16 split helpers ----------------
__device__ __forceinline__ void split_h2(float x, float y, uint32_t& hi, uint32_t& lo) {
    __half2 h = __floats2half2_rn(x, y);
    float rx = x - __low2float(h);
    float ry = y - __high2float(h);
    __half2 l = __floats2half2_rn(rx, ry);
    hi = *(uint32_t*)&h;
    lo = *(uint32_t*)&l;
}

__device__ __forceinline__ void mma_f16(float* d, const uint32_t* a, const uint32_t* b) {
    asm volatile(
        "mma.sync.aligned.m16n8k16.row.col.f32.f16.f16.f32 "
        "{%0,%1,%2,%3}, {%4,%5,%6,%7}, {%8,%9}, {%0,%1,%2,%3};\n"
        : "+f"(d[0]), "+f"(d[1]), "+f"(d[2]), "+f"(d[3])
        : "r"(a[0]), "r"(a[1]), "r"(a[2]), "r"(a[3]), "r"(b[0]), "r"(b[1]));
}

// ---------------- 3xFP16-split tensor GEMM (pre-split operands) ----------------
// C[M, BN] = A[M,K] @ B^T (+bias)(+relu). BM=128, BK=32, 256 threads (8 warps 4x2).
// B always [BN, K] K-major pre-split halves.
// AHALF: A pre-split halves [M, K]; else fp32 (split on load).
// EPI: 0 = C fp32 only; 1 = C fp32 + Ch fp16; 2 = C fp32 + split halves (Hs_hi/lo).
template<int BN, bool AHALF, bool BIAS, bool RELU, int EPI>
__global__ void __launch_bounds__(256) mma_gemm_k(
    const float* __restrict__ Af,
    const __half* __restrict__ Ahi, const __half* __restrict__ Alo,
    const __half* __restrict__ Bhi, const __half* __restrict__ Blo,
    const float* __restrict__ bias, float* __restrict__ C,
    __half* __restrict__ Ch, __half* __restrict__ Hs_hi, __half* __restrict__ Hs_lo,
    int M, int K)
{
    constexpr int BM = 128, BK = 32;
    constexpr int STR = 20;              // 16 half2 words + 4 pad (conflict-free frag LDS)
    constexpr int WN = BN / 2;
    constexpr int NTN = WN / 8;

    __shared__ uint32_t As_hi[BM * STR];
    __shared__ uint32_t As_lo[BM * STR];
    __shared__ uint32_t Bs_hi[BN * STR];
    __shared__ uint32_t Bs_lo[BN * STR];

    const int tid = threadIdx.x;
    const int warp = tid >> 5, lane = tid & 31;
    const int wm = warp >> 1, wn = warp & 1;
    const int grp = lane >> 2, tig = lane & 3;
    const int m0 = blockIdx.x * BM;

    float acc[2][NTN][4];
#pragma unroll
    for (int i = 0; i < 2; i++)
#pragma unroll
        for (int j = 0; j < NTN; j++)
#pragma unroll
            for (int q = 0; q < 4; q++) acc[i][j][q] = 0.f;

    for (int k0 = 0; k0 < K; k0 += BK) {
        // --- A tile: 128 rows x 32 halves = 512 uint4 per array, 2 iters ---
        if (AHALF) {
#pragma unroll
            for (int it = 0; it < 2; it++) {
                int idx = tid + it * 256;
                int r = idx >> 2, c4 = idx & 3;       // 4 uint4 (32 halves) per row
                uint4 vh = make_uint4(0u, 0u, 0u, 0u);
                uint4 vl = make_uint4(0u, 0u, 0u, 0u);
                if (m0 + r < M) {
                    size_t off = (size_t)(m0 + r) * K + k0 + c4 * 8;
                    vh = *(const uint4*)&Ahi[off];
                    vl = *(const uint4*)&Alo[off];
                }
                uint32_t* ph = &As_hi[r * STR + c4 * 4];
                ph[0] = vh.x; ph[1] = vh.y; ph[2] = vh.z; ph[3] = vh.w;
                uint32_t* pl = &As_lo[r * STR + c4 * 4];
                pl[0] = vl.x; pl[1] = vl.y; pl[2] = vl.z; pl[3] = vl.w;
            }
        } else {
#pragma unroll
            for (int it = 0; it < 4; it++) {
                int idx = tid + it * 256;
                int r = idx >> 3, c = idx & 7;
                float4 v = make_float4(0.f, 0.f, 0.f, 0.f);
                if (m0 + r < M) v = *(const float4*)&Af[(size_t)(m0 + r) * K + k0 + c * 4];
                uint32_t h01, l01, h23, l23;
                split_h2(v.x, v.y, h01, l01);
                split_h2(v.z, v.w, h23, l23);
                As_hi[r * STR + c * 2]     = h01;
                As_hi[r * STR + c * 2 + 1] = h23;
                As_lo[r * STR + c * 2]     = l01;
                As_lo[r * STR + c * 2 + 1] = l23;
            }
        }
        // --- B tile: BN rows x 32 halves = BN*4 uint4 per array ---
#pragma unroll
        for (int it = 0; it < (BN * 4) / 256; it++) {
            int idx = tid + it * 256;
            int n = idx >> 2, c4 = idx & 3;
            size_t off = (size_t)n * K + k0 + c4 * 8;
            uint4 vh = *(const uint4*)&Bhi[off];
            uint4 vl = *(const uint4*)&Blo[off];
            uint32_t* ph = &Bs_hi[n * STR + c4 * 4];
            ph[0] = vh.x; ph[1] = vh.y; ph[2] = vh.z; ph[3] = vh.w;
            uint32_t* pl = &Bs_lo[n * STR + c4 * 4];
            pl[0] = vl.x; pl[1] = vl.y; pl[2] = vl.z; pl[3] = vl.w;
        }
        __syncthreads();

#pragma unroll
        for (int kt = 0; kt < 2; kt++) {
            const int kb = kt * 8;
            uint32_t ah[2][4], al[2][4];
#pragma unroll
            for (int i = 0; i < 2; i++) {
                int row = wm * 32 + i * 16 + grp;
                ah[i][0] = As_hi[row * STR + kb + tig];
                ah[i][1] = As_hi[(row + 8) * STR + kb + tig];
                ah[i][2] = As_hi[row * STR + kb + tig + 4];
                ah[i][3] = As_hi[(row + 8) * STR + kb + tig + 4];
                al[i][0] = As_lo[row * STR + kb + tig];
                al[i][1] = As_lo[(row + 8) * STR + kb + tig];
                al[i][2] = As_lo[row * STR + kb + tig + 4];
                al[i][3] = As_lo[(row + 8) * STR + kb + tig + 4];
            }
#pragma unroll
            for (int j = 0; j < NTN; j++) {
                int n = wn * WN + j * 8 + grp;
                uint32_t bh[2], bl[2];
                bh[0] = Bs_hi[n * STR + kb + tig];
                bh[1] = Bs_hi[n * STR + kb + tig + 4];
                bl[0] = Bs_lo[n * STR + kb + tig];
                bl[1] = Bs_lo[n * STR + kb + tig + 4];
#pragma unroll
                for (int i = 0; i < 2; i++) {
                    mma_f16(acc[i][j], ah[i], bh);   // hi*hi
                    mma_f16(acc[i][j], al[i], bh);   // lo*hi
                    mma_f16(acc[i][j], ah[i], bl);   // hi*lo
                }
            }
        }
        __syncthreads();
    }

    // --- epilogue ---
#pragma unroll
    for (int i = 0; i < 2; i++) {
#pragma unroll
        for (int j = 0; j < NTN; j++) {
            int col = wn * WN + j * 8 + tig * 2;
            int row0 = m0 + wm * 32 + i * 16 + grp;
            int row1 = row0 + 8;
            float2 v0 = make_float2(acc[i][j][0], acc[i][j][1]);
            float2 v1 = make_float2(acc[i][j][2], acc[i][j][3]);
            if (BIAS) {
                float bx = bias[col], by = bias[col + 1];
                v0.x += bx; v0.y += by;
                v1.x += bx; v1.y += by;
            }
            if (RELU) {
                v0.x = fmaxf(v0.x, 0.f); v0.y = fmaxf(v0.y, 0.f);
                v1.x = fmaxf(v1.x, 0.f); v1.y = fmaxf(v1.y, 0.f);
            }
#pragma unroll
            for (int rr = 0; rr < 2; rr++) {
                int row = rr ? row1 : row0;
                float2 v = rr ? v1 : v0;
                if (row < M) {
                    *(float2*)&C[(size_t)row * BN + col] = v;
                    if (EPI == 1) {
                        *(__half2*)&Ch[(size_t)row * BN + col] = __floats2half2_rn(v.x, v.y);
                    }
                    if (EPI == 2) {
                        uint32_t hh, ll;
                        split_h2(v.x, v.y, hh, ll);
                        *(uint32_t*)&Hs_hi[(size_t)row * BN + col] = hh;
                        *(uint32_t*)&Hs_lo[(size_t)row * BN + col] = ll;
                    }
                }
            }
        }
    }
}

// ---------------- fused SpMM (fp16 gather) + self-loop + residual + ReLU + split-store ----
// 256 threads = 4 nodes x 64 lanes; each lane owns a feature pair.
__global__ void __launch_bounds__(256) spmm_res_k(const float* __restrict__ eps, int layer) {
    int node = blockIdx.x * 4 + (threadIdx.x >> 6);
    int f2 = threadIdx.x & 63;
    if (node >= NN) return;
    int s = g_indptr[node];
    int e = g_indptr[node + 1];
    const uint32_t* gh = (const uint32_t*)g_gh;

    float a0x = 0.f, a0y = 0.f, a1x = 0.f, a1y = 0.f;
    float a2x = 0.f, a2y = 0.f, a3x = 0.f, a3y = 0.f;
    int p = s;
    for (; p + 3 < e; p += 4) {
        int   c0 = g_cols[p];     float w0 = g_w[p];
        int   c1 = g_cols[p + 1]; float w1 = g_w[p + 1];
        int   c2 = g_cols[p + 2]; float w2 = g_w[p + 2];
        int   c3 = g_cols[p + 3]; float w3 = g_w[p + 3];
        float2 v0 = __half22float2(*(const __half2*)&gh[c0 * 64 + f2]);
        float2 v1 = __half22float2(*(const __half2*)&gh[c1 * 64 + f2]);
        float2 v2 = __half22float2(*(const __half2*)&gh[c2 * 64 + f2]);
        float2 v3 = __half22float2(*(const __half2*)&gh[c3 * 64 + f2]);
        a0x = fmaf(w0, v0.x, a0x); a0y = fmaf(w0, v0.y, a0y);
        a1x = fmaf(w1, v1.x, a1x); a1y = fmaf(w1, v1.y, a1y);
        a2x = fmaf(w2, v2.x, a2x); a2y = fmaf(w2, v2.y, a2y);
        a3x = fmaf(w3, v3.x, a3x); a3y = fmaf(w3, v3.y, a3y);
    }
    for (; p < e; p++) {
        int c0 = g_cols[p]; float w0 = g_w[p];
        float2 v0 = __half22float2(*(const __half2*)&gh[c0 * 64 + f2]);
        a0x = fmaf(w0, v0.x, a0x); a0y = fmaf(w0, v0.y, a0y);
    }
    float accx = (a0x + a1x) + (a2x + a3x);
    float accy = (a0y + a1y) + (a2y + a3y);

    size_t base = (size_t)node * HID + f2 * 2;
    float2 gi = *(const float2*)&g_g[base];
    float di = g_dinv[node];
    float c6 = 6.f - 3.f * di * di;
    float zx = fmaf(c6, gi.x, -3.f * accx);
    float zy = fmaf(c6, gi.y, -3.f * accy);
    float a = 1.f + tanhf(eps[layer]);
    float2 h0v = *(const float2*)&g_h0[base];
    h0v.x = fmaf(a, h0v.x, zx);
    h0v.y = fmaf(a, h0v.y, zy);
    *(float2*)&g_h0[base] = h0v;
    float hx = fmaxf(h0v.x, 0.f), hy = fmaxf(h0v.y, 0.f);
    uint32_t hh, ll;
    split_h2(hx, hy, hh, ll);
    *(uint32_t*)&g_hs_hi[base] = hh;
    *(uint32_t*)&g_hs_lo[base] = ll;
}

// ---------------- launch ----------------
extern "C" void kernel_launch(void* const* d_in, const int* in_sizes, int n_in,
                              void* d_out, int out_size) {
    const float* x   = (const float*)d_in[0];
    const float* W1  = (const float*)d_in[1];
    const float* b1  = (const float*)d_in[2];
    const float* Wr  = (const float*)d_in[3];
    const float* eps = (const float*)d_in[4];
    const float* W2  = (const float*)d_in[5];
    const float* b2  = (const float*)d_in[6];
    const int*   ei  = (const int*)d_in[7];
    float* out = (float*)d_out;

    float *h0p, *gp;
    __half *ghp, *hshp, *hslp;
    __half *w1h, *w1l, *wrh, *wrl, *w2h, *w2l;
    cudaGetSymbolAddress((void**)&h0p, g_h0);
    cudaGetSymbolAddress((void**)&gp,  g_g);
    cudaGetSymbolAddress((void**)&ghp, g_gh);
    cudaGetSymbolAddress((void**)&hshp, g_hs_hi);
    cudaGetSymbolAddress((void**)&hslp, g_hs_lo);
    cudaGetSymbolAddress((void**)&w1h, g_w1t_hi);
    cudaGetSymbolAddress((void**)&w1l, g_w1t_lo);
    cudaGetSymbolAddress((void**)&wrh, g_wrt_hi);
    cudaGetSymbolAddress((void**)&wrl, g_wrt_lo);
    cudaGetSymbolAddress((void**)&w2h, g_w2t_hi);
    cudaGetSymbolAddress((void**)&w2l, g_w2t_lo);

    int gblocks = (NN + 127) / 128;  // 391
    const int WTOT = HID * INF + NL * HID * HID + OUTF * HID;

    // #1 weight split, #2 detect+zero, #3 hist, #4 lin1 (ncu capture slot)
    split_w_k<<<(WTOT + 255) / 256, 256>>>(W1, Wr, W2);
    detect_zero_k<<<(NN + 255) / 256, 256>>>(ei);
    hist_k<<<(EE + 255) / 256, 256>>>(ei);

    // lin1: h0 = relu(x @ W1 + b1); also emit split halves for layer-0 GEMM
    mma_gemm_k<128, false, true, true, 2>
        <<<gblocks, 256>>>(x, nullptr, nullptr, w1h, w1l, b1, h0p,
                           nullptr, hshp, hslp, NN, INF);

    scan1_dinv_k<<<(NN + 1023) / 1024, 1024>>>();
    scan23_k<<<(NN + 1023) / 1024, 1024>>>();
    scatter_k<<<(EE + 255) / 256, 256>>>(ei);

    // --- 4 propagation layers ---
    for (int l = 0; l < NL; l++) {
        // g = h @ Wr[l]^T (A = split activations, B = pre-split Wr)
        mma_gemm_k<128, true, false, false, 1>
            <<<gblocks, 256>>>(nullptr, hshp, hslp,
                               wrh + (size_t)l * HID * HID, wrl + (size_t)l * HID * HID,
                               nullptr, gp, ghp, nullptr, nullptr, NN, HID);
        spmm_res_k<<<(NN + 3) / 4, 256>>>(eps, l);
    }

    // --- lin2: out = h @ W2 + b2 ---
    mma_gemm_k<64, true, true, false, 0>
        <<<gblocks, 256>>>(nullptr, hshp, hslp, w2h, w2l, b2, out,
                           nullptr, nullptr, nullptr, NN, HID);
}

// round 7
// speedup vs baseline: 1.5849x; 1.0277x over previous
#include <cuda_runtime.h>
#include <cuda_fp16.h>
#include <math.h>
#include <stdint.h>

// Problem constants (fixed shapes)
#define NN   50000
#define EE   800000
#define INF  256
#define HID  128
#define OUTF 64
#define NL   4

// ---------------- static device scratch ----------------
__device__ float  g_h0[NN * HID];       // residual state (fp32)
__device__ __half g_hs_hi[NN * HID];    // split activations hi
__device__ __half g_hs_lo[NN * HID];    // split activations lo
__device__ __half g_xs_hi[NN * INF];    // split input x hi
__device__ __half g_xs_lo[NN * INF];    // split input x lo
__device__ float  g_g [NN * HID];       // GEMM output g (fp32, self-loop term)
__device__ __half g_gh[NN * HID];       // fp16 copy of g for SpMM gather
__device__ float  g_w [EE];
__device__ float  g_dinv[NN];
__device__ int    g_counts[NN];
__device__ int    g_incl[NN];
__device__ int    g_indptr[NN + 1];
__device__ int    g_cursor[NN];
__device__ int    g_cols[EE];
__device__ int    g_chunksums[64];
__device__ int    g_is64;

// pre-split weights (K-major: B[n][k])
__device__ __half g_w1t_hi[HID * INF];
__device__ __half g_w1t_lo[HID * INF];
__device__ __half g_wrt_hi[NL * HID * HID];
__device__ __half g_wrt_lo[NL * HID * HID];
__device__ __half g_w2t_hi[OUTF * HID];
__device__ __half g_w2t_lo[OUTF * HID];

// ---------------- split helpers ----------------
__device__ __forceinline__ void split_h2(float x, float y, uint32_t& hi, uint32_t& lo) {
    __half2 h = __floats2half2_rn(x, y);
    float rx = x - __low2float(h);
    float ry = y - __high2float(h);
    __half2 l = __floats2half2_rn(rx, ry);
    hi = *(uint32_t*)&h;
    lo = *(uint32_t*)&l;
}

// ---------------- weight split prep ----------------
__global__ void split_w_k(const float* __restrict__ W1, const float* __restrict__ Wr,
                          const float* __restrict__ W2) {
    int idx = blockIdx.x * blockDim.x + threadIdx.x;
    float v;
    __half* hi;
    __half* lo;
    int oidx;
    if (idx < HID * INF) {                       // W1^T: out[n*256+k] = W1[k*128+n]
        int n = idx >> 8, k = idx & 255;
        v = W1[k * HID + n];
        hi = g_w1t_hi; lo = g_w1t_lo; oidx = idx;
    } else if (idx < HID * INF + NL * HID * HID) {
        int j = idx - HID * INF;
        v = Wr[j];
        hi = g_wrt_hi; lo = g_wrt_lo; oidx = j;
    } else if (idx < HID * INF + NL * HID * HID + OUTF * HID) {
        int j = idx - HID * INF - NL * HID * HID;
        int n = j >> 7, k = j & 127;
        v = W2[k * OUTF + n];
        hi = g_w2t_hi; lo = g_w2t_lo; oidx = j;
    } else return;
    __half h = __float2half_rn(v);
    hi[oidx] = h;
    lo[oidx] = __float2half_rn(v - __half2float(h));
}

// ---------------- input x split prep ----------------
__global__ void split_x_k(const float* __restrict__ x) {
    int i = blockIdx.x * blockDim.x + threadIdx.x;   // pair index
    if (i >= NN * INF / 2) return;
    float2 v = *(const float2*)&x[(size_t)i * 2];
    uint32_t h, l;
    split_h2(v.x, v.y, h, l);
    *(uint32_t*)&g_xs_hi[(size_t)i * 2] = h;
    *(uint32_t*)&g_xs_lo[(size_t)i * 2] = l;
}

// ---------------- edge dtype detect + zero counts ----------------
__global__ void detect_zero_k(const int* __restrict__ ei32) {
    int i = blockIdx.x * blockDim.x + threadIdx.x;
    if (i < NN) g_counts[i] = 0;
    if (blockIdx.x == 0) {
        __shared__ int s_any;
        if (threadIdx.x == 0) s_any = 0;
        __syncthreads();
        int any = 0;
        for (int j = 1 + 2 * threadIdx.x; j < 8192; j += 2 * 256) any |= ei32[j];
        if (any) atomicOr(&s_any, 1);
        __syncthreads();
        if (threadIdx.x == 0) g_is64 = (s_any == 0) ? 1 : 0;
    }
}

__device__ __forceinline__ int edge_at(const int* __restrict__ ei32, int idx) {
    return g_is64 ? ei32[2 * idx] : ei32[idx];
}

// ---------------- graph build ----------------
__global__ void hist_k(const int* __restrict__ ei32) {
    int e = blockIdx.x * blockDim.x + threadIdx.x;
    if (e < EE) atomicAdd(&g_counts[edge_at(ei32, e)], 1);
}

__global__ void scan1_dinv_k() {
    __shared__ int s[1024];
    int t = threadIdx.x;
    int base = blockIdx.x * 1024;
    int v = (base + t < NN) ? g_counts[base + t] : 0;
    if (base + t < NN) g_dinv[base + t] = rsqrtf((float)(v + 1));
    s[t] = v;
    __syncthreads();
    for (int off = 1; off < 1024; off <<= 1) {
        int x = (t >= off) ? s[t - off] : 0;
        __syncthreads();
        s[t] += x;
        __syncthreads();
    }
    if (base + t < NN) g_incl[base + t] = s[t];
    if (t == 1023) g_chunksums[blockIdx.x] = s[1023];
}

__global__ void scan23_k() {
    __shared__ int s_off;
    int b = blockIdx.x;
    if (threadIdx.x < 32) {
        int v = 0;
        for (int k = threadIdx.x; k < b; k += 32) v += g_chunksums[k];
#pragma unroll
        for (int o = 16; o; o >>= 1) v += __shfl_down_sync(0xffffffffu, v, o);
        if (threadIdx.x == 0) s_off = v;
    }
    __syncthreads();
    int i = b * 1024 + threadIdx.x;
    if (i < NN) {
        int v = s_off + g_incl[i] - g_counts[i];
        g_indptr[i] = v;
        g_cursor[i] = v;
        if (i == 0) g_indptr[NN] = EE;
    }
}

__global__ void scatter_k(const int* __restrict__ ei32) {
    int e = blockIdx.x * blockDim.x + threadIdx.x;
    if (e < EE) {
        int r = edge_at(ei32, e);
        int c = edge_at(ei32, EE + e);
        int pos = atomicAdd(&g_cursor[r], 1);
        g_cols[pos] = c;
        g_w[pos] = g_dinv[r] * g_dinv[c];
    }
}

// ---------------- mma helpers ----------------
__device__ __forceinline__ void mma_f16(float* d, const uint32_t* a, const uint32_t* b) {
    asm volatile(
        "mma.sync.aligned.m16n8k16.row.col.f32.f16.f16.f32 "
        "{%0,%1,%2,%3}, {%4,%5,%6,%7}, {%8,%9}, {%0,%1,%2,%3};\n"
        : "+f"(d[0]), "+f"(d[1]), "+f"(d[2]), "+f"(d[3])
        : "r"(a[0]), "r"(a[1]), "r"(a[2]), "r"(a[3]), "r"(b[0]), "r"(b[1]));
}

__device__ __forceinline__ void cpa16(void* s, const void* g) {
    uint32_t sa = (uint32_t)__cvta_generic_to_shared(s);
    asm volatile("cp.async.cg.shared.global [%0], [%1], 16;" :: "r"(sa), "l"(g));
}
#define CP_COMMIT() asm volatile("cp.async.commit_group;" ::: "memory")
#define CP_WAIT(n)  asm volatile("cp.async.wait_group %0;" :: "n"(n) : "memory")

// ---------------- 3xFP16-split tensor GEMM (pre-split, cp.async double-buffered) ----------
// C[M, BN] = A[M,K] @ B^T (+bias)(+relu). BM=128, BK=32, 256 threads (8 warps 4x2), 2 CTA/SM.
// A [M,K] and B [BN,K] are pre-split half arrays (K-major).
// EPI: 0 = C fp32; 1 = C fp32 + Ch fp16; 2 = C fp32 + split halves.
template<int BN, bool BIAS, bool RELU, int EPI>
__global__ void __launch_bounds__(256, 2) mma_gemm_k(
    const __half* __restrict__ Ahi, const __half* __restrict__ Alo,
    const __half* __restrict__ Bhi, const __half* __restrict__ Blo,
    const float* __restrict__ bias, float* __restrict__ C,
    __half* __restrict__ Ch, __half* __restrict__ Hs_hi, __half* __restrict__ Hs_lo,
    int M, int K)
{
    constexpr int BM = 128;
    constexpr int STR = 20;              // 16 half2 words + 4 pad (conflict-free frag LDS)
    constexpr int AW = BM * STR;         // words per A array (2560)
    constexpr int BW = BN * STR;
    constexpr int STAGE = 2 * AW + 2 * BW;
    constexpr int WN = BN / 2;
    constexpr int NTN = WN / 8;

    extern __shared__ uint32_t sm[];

    const int tid = threadIdx.x;
    const int warp = tid >> 5, lane = tid & 31;
    const int wm = warp >> 1, wn = warp & 1;
    const int grp = lane >> 2, tig = lane & 3;
    const int m0 = blockIdx.x * BM;
    const int nchunks = K >> 5;          // BK = 32

    // per-thread load coordinates
    const int a_r = tid >> 2, a_c4 = tid & 3;           // +128 rows on 2nd iter
    const int a_row0 = min(m0 + a_r, M - 1);
    const int a_row1 = min(m0 + a_r + 64, M - 1);       // (tid+256)>>2 = a_r+64

    auto load_stage = [&](int st, int k0) {
        uint32_t* base = sm + st * STAGE;
        // A tile: 128 rows x 32 halves; 512 uint4 per array, 2 iters
        {
            size_t off0 = (size_t)a_row0 * K + k0 + a_c4 * 8;
            size_t off1 = (size_t)a_row1 * K + k0 + a_c4 * 8;
            cpa16(&base[a_r * STR + a_c4 * 4],            &Ahi[off0]);
            cpa16(&base[AW + a_r * STR + a_c4 * 4],       &Alo[off0]);
            cpa16(&base[(a_r + 64) * STR + a_c4 * 4],     &Ahi[off1]);
            cpa16(&base[AW + (a_r + 64) * STR + a_c4 * 4],&Alo[off1]);
        }
        // B tile: BN rows x 32 halves
#pragma unroll
        for (int it = 0; it < (BN * 4) / 256; it++) {
            int idx = tid + it * 256;
            int n = idx >> 2, c4 = idx & 3;
            size_t off = (size_t)n * K + k0 + c4 * 8;
            cpa16(&base[2 * AW + n * STR + c4 * 4],      &Bhi[off]);
            cpa16(&base[2 * AW + BW + n * STR + c4 * 4], &Blo[off]);
        }
    };

    float acc[2][NTN][4];
#pragma unroll
    for (int i = 0; i < 2; i++)
#pragma unroll
        for (int j = 0; j < NTN; j++)
#pragma unroll
            for (int q = 0; q < 4; q++) acc[i][j][q] = 0.f;

    load_stage(0, 0);
    CP_COMMIT();

    for (int ck = 0; ck < nchunks; ck++) {
        if (ck + 1 < nchunks) {
            load_stage((ck + 1) & 1, (ck + 1) << 5);
            CP_COMMIT();
            CP_WAIT(1);
        } else {
            CP_WAIT(0);
        }
        __syncthreads();

        const uint32_t* As_hi = sm + (ck & 1) * STAGE;
        const uint32_t* As_lo = As_hi + AW;
        const uint32_t* Bs_hi = As_hi + 2 * AW;
        const uint32_t* Bs_lo = Bs_hi + BW;

#pragma unroll
        for (int kt = 0; kt < 2; kt++) {
            const int kb = kt * 8;
            uint32_t ah[2][4], al[2][4];
#pragma unroll
            for (int i = 0; i < 2; i++) {
                int row = wm * 32 + i * 16 + grp;
                ah[i][0] = As_hi[row * STR + kb + tig];
                ah[i][1] = As_hi[(row + 8) * STR + kb + tig];
                ah[i][2] = As_hi[row * STR + kb + tig + 4];
                ah[i][3] = As_hi[(row + 8) * STR + kb + tig + 4];
                al[i][0] = As_lo[row * STR + kb + tig];
                al[i][1] = As_lo[(row + 8) * STR + kb + tig];
                al[i][2] = As_lo[row * STR + kb + tig + 4];
                al[i][3] = As_lo[(row + 8) * STR + kb + tig + 4];
            }
#pragma unroll
            for (int j = 0; j < NTN; j++) {
                int n = wn * WN + j * 8 + grp;
                uint32_t bh[2], bl[2];
                bh[0] = Bs_hi[n * STR + kb + tig];
                bh[1] = Bs_hi[n * STR + kb + tig + 4];
                bl[0] = Bs_lo[n * STR + kb + tig];
                bl[1] = Bs_lo[n * STR + kb + tig + 4];
#pragma unroll
                for (int i = 0; i < 2; i++) {
                    mma_f16(acc[i][j], ah[i], bh);   // hi*hi
                    mma_f16(acc[i][j], al[i], bh);   // lo*hi
                    mma_f16(acc[i][j], ah[i], bl);   // hi*lo
                }
            }
        }
        __syncthreads();
    }

    // --- epilogue ---
#pragma unroll
    for (int i = 0; i < 2; i++) {
#pragma unroll
        for (int j = 0; j < NTN; j++) {
            int col = wn * WN + j * 8 + tig * 2;
            int row0 = m0 + wm * 32 + i * 16 + grp;
            int row1 = row0 + 8;
            float2 v0 = make_float2(acc[i][j][0], acc[i][j][1]);
            float2 v1 = make_float2(acc[i][j][2], acc[i][j][3]);
            if (BIAS) {
                float bx = bias[col], by = bias[col + 1];
                v0.x += bx; v0.y += by;
                v1.x += bx; v1.y += by;
            }
            if (RELU) {
                v0.x = fmaxf(v0.x, 0.f); v0.y = fmaxf(v0.y, 0.f);
                v1.x = fmaxf(v1.x, 0.f); v1.y = fmaxf(v1.y, 0.f);
            }
#pragma unroll
            for (int rr = 0; rr < 2; rr++) {
                int row = rr ? row1 : row0;
                float2 v = rr ? v1 : v0;
                if (row < M) {
                    *(float2*)&C[(size_t)row * BN + col] = v;
                    if (EPI == 1) {
                        *(__half2*)&Ch[(size_t)row * BN + col] = __floats2half2_rn(v.x, v.y);
                    }
                    if (EPI == 2) {
                        uint32_t hh, ll;
                        split_h2(v.x, v.y, hh, ll);
                        *(uint32_t*)&Hs_hi[(size_t)row * BN + col] = hh;
                        *(uint32_t*)&Hs_lo[(size_t)row * BN + col] = ll;
                    }
                }
            }
        }
    }
}

// ---------------- fused SpMM (fp16 gather) + self-loop + residual + ReLU + split-store ----
__global__ void __launch_bounds__(256) spmm_res_k(const float* __restrict__ eps, int layer) {
    int node = blockIdx.x * 4 + (threadIdx.x >> 6);
    int f2 = threadIdx.x & 63;
    if (node >= NN) return;
    int s = g_indptr[node];
    int e = g_indptr[node + 1];
    const uint32_t* gh = (const uint32_t*)g_gh;

    float a0x = 0.f, a0y = 0.f, a1x = 0.f, a1y = 0.f;
    float a2x = 0.f, a2y = 0.f, a3x = 0.f, a3y = 0.f;
    int p = s;
    for (; p + 3 < e; p += 4) {
        int   c0 = g_cols[p];     float w0 = g_w[p];
        int   c1 = g_cols[p + 1]; float w1 = g_w[p + 1];
        int   c2 = g_cols[p + 2]; float w2 = g_w[p + 2];
        int   c3 = g_cols[p + 3]; float w3 = g_w[p + 3];
        float2 v0 = __half22float2(*(const __half2*)&gh[c0 * 64 + f2]);
        float2 v1 = __half22float2(*(const __half2*)&gh[c1 * 64 + f2]);
        float2 v2 = __half22float2(*(const __half2*)&gh[c2 * 64 + f2]);
        float2 v3 = __half22float2(*(const __half2*)&gh[c3 * 64 + f2]);
        a0x = fmaf(w0, v0.x, a0x); a0y = fmaf(w0, v0.y, a0y);
        a1x = fmaf(w1, v1.x, a1x); a1y = fmaf(w1, v1.y, a1y);
        a2x = fmaf(w2, v2.x, a2x); a2y = fmaf(w2, v2.y, a2y);
        a3x = fmaf(w3, v3.x, a3x); a3y = fmaf(w3, v3.y, a3y);
    }
    for (; p < e; p++) {
        int c0 = g_cols[p]; float w0 = g_w[p];
        float2 v0 = __half22float2(*(const __half2*)&gh[c0 * 64 + f2]);
        a0x = fmaf(w0, v0.x, a0x); a0y = fmaf(w0, v0.y, a0y);
    }
    float accx = (a0x + a1x) + (a2x + a3x);
    float accy = (a0y + a1y) + (a2y + a3y);

    size_t base = (size_t)node * HID + f2 * 2;
    float2 gi = *(const float2*)&g_g[base];
    float di = g_dinv[node];
    float c6 = 6.f - 3.f * di * di;
    float zx = fmaf(c6, gi.x, -3.f * accx);
    float zy = fmaf(c6, gi.y, -3.f * accy);
    float a = 1.f + tanhf(eps[layer]);
    float2 h0v = *(const float2*)&g_h0[base];
    h0v.x = fmaf(a, h0v.x, zx);
    h0v.y = fmaf(a, h0v.y, zy);
    *(float2*)&g_h0[base] = h0v;
    float hx = fmaxf(h0v.x, 0.f), hy = fmaxf(h0v.y, 0.f);
    uint32_t hh, ll;
    split_h2(hx, hy, hh, ll);
    *(uint32_t*)&g_hs_hi[base] = hh;
    *(uint32_t*)&g_hs_lo[base] = ll;
}

// ---------------- launch ----------------
extern "C" void kernel_launch(void* const* d_in, const int* in_sizes, int n_in,
                              void* d_out, int out_size) {
    const float* x   = (const float*)d_in[0];
    const float* W1  = (const float*)d_in[1];
    const float* b1  = (const float*)d_in[2];
    const float* Wr  = (const float*)d_in[3];
    const float* eps = (const float*)d_in[4];
    const float* W2  = (const float*)d_in[5];
    const float* b2  = (const float*)d_in[6];
    const int*   ei  = (const int*)d_in[7];
    float* out = (float*)d_out;

    float *h0p, *gp;
    __half *ghp, *hshp, *hslp, *xshp, *xslp;
    __half *w1h, *w1l, *wrh, *wrl, *w2h, *w2l;
    cudaGetSymbolAddress((void**)&h0p, g_h0);
    cudaGetSymbolAddress((void**)&gp,  g_g);
    cudaGetSymbolAddress((void**)&ghp, g_gh);
    cudaGetSymbolAddress((void**)&hshp, g_hs_hi);
    cudaGetSymbolAddress((void**)&hslp, g_hs_lo);
    cudaGetSymbolAddress((void**)&xshp, g_xs_hi);
    cudaGetSymbolAddress((void**)&xslp, g_xs_lo);
    cudaGetSymbolAddress((void**)&w1h, g_w1t_hi);
    cudaGetSymbolAddress((void**)&w1l, g_w1t_lo);
    cudaGetSymbolAddress((void**)&wrh, g_wrt_hi);
    cudaGetSymbolAddress((void**)&wrl, g_wrt_lo);
    cudaGetSymbolAddress((void**)&w2h, g_w2t_hi);
    cudaGetSymbolAddress((void**)&w2l, g_w2t_lo);

    // dynamic smem: 2 stages x (2*A + 2*B) words x 4B
    const int SMEM_N128 = 2 * (2 * 128 * 20 + 2 * 128 * 20) * 4;  // 81920
    const int SMEM_N64  = 2 * (2 * 128 * 20 + 2 * 64 * 20) * 4;   // 61440
    static bool attr_done = false;
    if (!attr_done) {
        cudaFuncSetAttribute(mma_gemm_k<128, true, true, 2>,
                             cudaFuncAttributeMaxDynamicSharedMemorySize, SMEM_N128);
        cudaFuncSetAttribute(mma_gemm_k<128, false, false, 1>,
                             cudaFuncAttributeMaxDynamicSharedMemorySize, SMEM_N128);
        cudaFuncSetAttribute(mma_gemm_k<64, true, false, 0>,
                             cudaFuncAttributeMaxDynamicSharedMemorySize, SMEM_N64);
        attr_done = true;
    }

    int gblocks = (NN + 127) / 128;  // 391
    const int WTOT = HID * INF + NL * HID * HID + OUTF * HID;

    split_w_k<<<(WTOT + 255) / 256, 256>>>(W1, Wr, W2);
    split_x_k<<<(NN * INF / 2 + 255) / 256, 256>>>(x);
    detect_zero_k<<<(NN + 255) / 256, 256>>>(ei);
    hist_k<<<(EE + 255) / 256, 256>>>(ei);

    // lin1: h0 = relu(x @ W1 + b1); emit split halves for layer-0 GEMM
    mma_gemm_k<128, true, true, 2>
        <<<gblocks, 256, SMEM_N128>>>(xshp, xslp, w1h, w1l, b1, h0p,
                                      nullptr, hshp, hslp, NN, INF);

    scan1_dinv_k<<<(NN + 1023) / 1024, 1024>>>();
    scan23_k<<<(NN + 1023) / 1024, 1024>>>();
    scatter_k<<<(EE + 255) / 256, 256>>>(ei);

    // --- 4 propagation layers ---
    for (int l = 0; l < NL; l++) {
        mma_gemm_k<128, false, false, 1>
            <<<gblocks, 256, SMEM_N128>>>(hshp, hslp,
                                          wrh + (size_t)l * HID * HID,
                                          wrl + (size_t)l * HID * HID,
                                          nullptr, gp, ghp, nullptr, nullptr, NN, HID);
        spmm_res_k<<<(NN + 3) / 4, 256>>>(eps, l);
    }

    // --- lin2: out = h @ W2 + b2 ---
    mma_gemm_k<64, true, false, 0>
        <<<gblocks, 256, SMEM_N64>>>(hshp, hslp, w2h, w2l, b2, out,
                                     nullptr, nullptr, nullptr, NN, HID);
}